// round 3
// baseline (speedup 1.0000x reference)
#include <cuda_runtime.h>
#include <math.h>

// Problem constants
constexpr int BATCH = 4;
constexpr int NTOK  = 4096;   // h*w
constexpr int CD    = 128;    // channels (C_IN == C_INNER)

// Attention tiling
constexpr int BQ = 128;       // query tile per CTA
constexpr int BK = 64;        // key tile per iteration
constexpr int PQ = BQ + 4;    // smem pitches (floats), multiples of 4 for float4
constexpr int PK = BK + 4;
constexpr int PV = CD + 4;
constexpr int PP = BQ + 4;

// Scratch (device globals: allocation-free rule)
__device__ float g_WT[3 * CD * CD];   // Wq^T, Wk^T, Wv^T as [c][o]
__device__ float g_WoT[CD * CD];      // Wo^T as [c][o]
__device__ float g_Q[BATCH * CD * NTOK];   // [b][d][tok]  (channel-major)
__device__ float g_K[BATCH * CD * NTOK];   // [b][d][tok]
__device__ float g_V[BATCH * NTOK * CD];   // [b][tok][d]  (token-major)
__device__ float g_O[BATCH * CD * NTOK];   // [b][d][tok]

// ---------------------------------------------------------------------------
// Kernel 0: transpose the four 128x128 weight matrices (tiny; keeps main GEMM
// smem loads coalesced + conflict-free).
// ---------------------------------------------------------------------------
__global__ void k_transpose_w(const float* __restrict__ Wq,
                              const float* __restrict__ Wk,
                              const float* __restrict__ Wv,
                              const float* __restrict__ Wo) {
    const float* src;
    float* dst;
    int w = blockIdx.x;
    if      (w == 0) { src = Wq; dst = g_WT;               }
    else if (w == 1) { src = Wk; dst = g_WT + CD * CD;     }
    else if (w == 2) { src = Wv; dst = g_WT + 2 * CD * CD; }
    else             { src = Wo; dst = g_WoT;              }
    for (int idx = threadIdx.x; idx < CD * CD; idx += blockDim.x) {
        int o = idx / CD, c = idx % CD;
        dst[c * CD + o] = src[idx];  // read coalesced, 64KB each: negligible
    }
}

// ---------------------------------------------------------------------------
// Kernel 1: fused QKV 1x1 convs. One CTA = one batch x 128-token tile, all 128
// output channels, looping the three weights while reusing the X tile in smem.
// Q,K stored channel-major; V stored token-major.
// smem: Ws[128][132] + Xs[128][132]  (dynamic, 135168 B)
// ---------------------------------------------------------------------------
constexpr int SM_GEMM = 2 * CD * (CD + 4) * 4;

__global__ __launch_bounds__(256, 1)
void k_qkv(const float* __restrict__ x,
           const float* __restrict__ bq,
           const float* __restrict__ bk,
           const float* __restrict__ bv) {
    extern __shared__ float sm[];
    float* Ws = sm;                  // [c][o], pitch CD+4
    float* Xs = sm + CD * (CD + 4);  // [c][p], pitch CD+4
    constexpr int PW = CD + 4;

    const int b  = blockIdx.y;
    const int p0 = blockIdx.x * 128;
    const int tid = threadIdx.x;
    const int ty = tid >> 4, tx = tid & 15;

    // Load X tile [128 c][128 p] (coalesced float4)
    for (int idx = tid; idx < CD * 32; idx += 256) {
        int c = idx >> 5, c4 = (idx & 31) * 4;
        *(float4*)(Xs + c * PW + c4) =
            *(const float4*)(x + ((size_t)(b * CD + c)) * NTOK + p0 + c4);
    }

    for (int w = 0; w < 3; w++) {
        __syncthreads();
        for (int idx = tid; idx < CD * 32; idx += 256) {
            int c = idx >> 5, c4 = (idx & 31) * 4;
            *(float4*)(Ws + c * PW + c4) =
                *(const float4*)(g_WT + w * CD * CD + c * CD + c4);
        }
        __syncthreads();

        float acc[8][8];
#pragma unroll
        for (int i = 0; i < 8; i++)
#pragma unroll
            for (int j = 0; j < 8; j++) acc[i][j] = 0.f;

#pragma unroll 4
        for (int c = 0; c < CD; c++) {
            float4 w0 = *(float4*)(Ws + c * PW + ty * 8);
            float4 w1 = *(float4*)(Ws + c * PW + ty * 8 + 4);
            float4 x0 = *(float4*)(Xs + c * PW + tx * 8);
            float4 x1 = *(float4*)(Xs + c * PW + tx * 8 + 4);
            float wr[8] = {w0.x, w0.y, w0.z, w0.w, w1.x, w1.y, w1.z, w1.w};
            float xr[8] = {x0.x, x0.y, x0.z, x0.w, x1.x, x1.y, x1.z, x1.w};
#pragma unroll
            for (int i = 0; i < 8; i++)
#pragma unroll
                for (int j = 0; j < 8; j++) acc[i][j] += wr[i] * xr[j];
        }

        const float* bias = (w == 0) ? bq : (w == 1) ? bk : bv;
#pragma unroll
        for (int i = 0; i < 8; i++) {
            float bb = bias[ty * 8 + i];
#pragma unroll
            for (int j = 0; j < 8; j++) acc[i][j] += bb;
        }

        if (w < 2) {  // channel-major store
            float* dst = (w == 0) ? g_Q : g_K;
#pragma unroll
            for (int i = 0; i < 8; i++) {
                float* r = dst + ((size_t)(b * CD + ty * 8 + i)) * NTOK + p0 + tx * 8;
                *(float4*)(r)     = make_float4(acc[i][0], acc[i][1], acc[i][2], acc[i][3]);
                *(float4*)(r + 4) = make_float4(acc[i][4], acc[i][5], acc[i][6], acc[i][7]);
            }
        } else {      // token-major store for V
#pragma unroll
            for (int j = 0; j < 8; j++) {
                float* r = g_V + ((size_t)(b * NTOK + p0 + tx * 8 + j)) * CD + ty * 8;
                *(float4*)(r)     = make_float4(acc[0][j], acc[1][j], acc[2][j], acc[3][j]);
                *(float4*)(r + 4) = make_float4(acc[4][j], acc[5][j], acc[6][j], acc[7][j]);
            }
        }
    }
}

// ---------------------------------------------------------------------------
// Kernel 2: flash attention, fp32. CTA = one batch x 128-query tile; iterates
// 64-key tiles with online softmax. 256 threads = 16x16; per-thread microtiles:
// S: 4k x 8q, O: 8d x 8q.
// smem: Qs[128d][132] + Ks[128d][68] + Vs[64k][132] + Ps[64k][132] = 169984 B
// ---------------------------------------------------------------------------
constexpr int SM_ATTN = (CD * PQ + CD * PK + BK * PV + BK * PP) * 4;

__global__ __launch_bounds__(256, 1)
void k_attn() {
    extern __shared__ float sm[];
    float* Qs = sm;                 // [d][q]
    float* Ks = Qs + CD * PQ;       // [d][k]
    float* Vs = Ks + CD * PK;       // [k][d]
    float* Ps = Vs + BK * PV;       // [k][q]

    const int b  = blockIdx.y;
    const int q0 = blockIdx.x * BQ;
    const int tid = threadIdx.x;
    const int ty = tid >> 4, tx = tid & 15;

    // Load Q tile [128 d][128 q] once (native channel-major layout: no transpose)
    for (int idx = tid; idx < CD * (BQ / 4); idx += 256) {
        int d = idx >> 5, c4 = (idx & 31) * 4;
        *(float4*)(Qs + d * PQ + c4) =
            *(const float4*)(g_Q + ((size_t)(b * CD + d)) * NTOK + q0 + c4);
    }

    float m[8], l[8], o_acc[8][8];  // o_acc[d][q]
#pragma unroll
    for (int i = 0; i < 8; i++) {
        m[i] = -INFINITY; l[i] = 0.f;
#pragma unroll
        for (int j = 0; j < 8; j++) o_acc[j][i] = 0.f;
    }

    for (int kt = 0; kt < NTOK / BK; kt++) {
        const int k0 = kt * BK;
        __syncthreads();  // previous O-GEMM done reading Vs/Ps
        // K tile [128 d][64 k]
        for (int idx = tid; idx < CD * (BK / 4); idx += 256) {
            int d = idx >> 4, c4 = (idx & 15) * 4;
            *(float4*)(Ks + d * PK + c4) =
                *(const float4*)(g_K + ((size_t)(b * CD + d)) * NTOK + k0 + c4);
        }
        // V tile [64 k][128 d]
        for (int idx = tid; idx < BK * (CD / 4); idx += 256) {
            int k = idx >> 5, c4 = (idx & 31) * 4;
            *(float4*)(Vs + k * PV + c4) =
                *(const float4*)(g_V + ((size_t)(b * NTOK + k0 + k)) * CD + c4);
        }
        __syncthreads();

        // S = Q^T K  -> s[j(k)][i(q)]
        float s[4][8];
#pragma unroll
        for (int j = 0; j < 4; j++)
#pragma unroll
            for (int i = 0; i < 8; i++) s[j][i] = 0.f;

#pragma unroll 4
        for (int kk = 0; kk < CD; kk++) {
            float4 a0 = *(float4*)(Qs + kk * PQ + ty * 8);
            float4 a1 = *(float4*)(Qs + kk * PQ + ty * 8 + 4);
            float4 b4 = *(float4*)(Ks + kk * PK + tx * 4);
            float ar[8] = {a0.x, a0.y, a0.z, a0.w, a1.x, a1.y, a1.z, a1.w};
            float br[4] = {b4.x, b4.y, b4.z, b4.w};
#pragma unroll
            for (int j = 0; j < 4; j++)
#pragma unroll
                for (int i = 0; i < 8; i++) s[j][i] += br[j] * ar[i];
        }

        // Online softmax per q-row (row spread over 16 lanes with same ty)
#pragma unroll
        for (int i = 0; i < 8; i++) {
            float mx = fmaxf(fmaxf(s[0][i], s[1][i]), fmaxf(s[2][i], s[3][i]));
#pragma unroll
            for (int off = 8; off >= 1; off >>= 1)
                mx = fmaxf(mx, __shfl_xor_sync(0xffffffffu, mx, off, 16));
            float nm = fmaxf(m[i], mx);
            float sc = __expf(m[i] - nm);
            m[i] = nm;
            float rs = 0.f;
#pragma unroll
            for (int j = 0; j < 4; j++) { s[j][i] = __expf(s[j][i] - nm); rs += s[j][i]; }
#pragma unroll
            for (int off = 8; off >= 1; off >>= 1)
                rs += __shfl_xor_sync(0xffffffffu, rs, off, 16);
            l[i] = l[i] * sc + rs;
#pragma unroll
            for (int j = 0; j < 8; j++) o_acc[j][i] *= sc;
        }

        // Stage P into smem as [k][q]
#pragma unroll
        for (int j = 0; j < 4; j++) {
            float* r = Ps + (tx * 4 + j) * PP + ty * 8;
            *(float4*)(r)     = make_float4(s[j][0], s[j][1], s[j][2], s[j][3]);
            *(float4*)(r + 4) = make_float4(s[j][4], s[j][5], s[j][6], s[j][7]);
        }
        __syncthreads();

        // O += P^T V   (inner dim = k)
#pragma unroll 4
        for (int kk = 0; kk < BK; kk++) {
            float4 p0 = *(float4*)(Ps + kk * PP + ty * 8);
            float4 p1 = *(float4*)(Ps + kk * PP + ty * 8 + 4);
            float4 v0 = *(float4*)(Vs + kk * PV + tx * 8);
            float4 v1 = *(float4*)(Vs + kk * PV + tx * 8 + 4);
            float pr[8] = {p0.x, p0.y, p0.z, p0.w, p1.x, p1.y, p1.z, p1.w};
            float vr[8] = {v0.x, v0.y, v0.z, v0.w, v1.x, v1.y, v1.z, v1.w};
#pragma unroll
            for (int j = 0; j < 8; j++)
#pragma unroll
                for (int i = 0; i < 8; i++) o_acc[j][i] += vr[j] * pr[i];
        }
    }

    // Normalize and store channel-major (native for the Wo GEMM)
#pragma unroll
    for (int i = 0; i < 8; i++) {
        float inv = 1.0f / l[i];
#pragma unroll
        for (int j = 0; j < 8; j++) o_acc[j][i] *= inv;
    }
#pragma unroll
    for (int j = 0; j < 8; j++) {
        float* r = g_O + ((size_t)(b * CD + tx * 8 + j)) * NTOK + q0 + ty * 8;
        *(float4*)(r)     = make_float4(o_acc[j][0], o_acc[j][1], o_acc[j][2], o_acc[j][3]);
        *(float4*)(r + 4) = make_float4(o_acc[j][4], o_acc[j][5], o_acc[j][6], o_acc[j][7]);
    }
}

// ---------------------------------------------------------------------------
// Kernel 3: out = Wo @ O + bo + x  (residual fused)
// ---------------------------------------------------------------------------
__global__ __launch_bounds__(256, 1)
void k_out(const float* __restrict__ x,
           const float* __restrict__ bo,
           float* __restrict__ out) {
    extern __shared__ float sm[];
    float* Ws = sm;                  // [c][o]
    float* Os = sm + CD * (CD + 4);  // [c][p]
    constexpr int PW = CD + 4;

    const int b  = blockIdx.y;
    const int p0 = blockIdx.x * 128;
    const int tid = threadIdx.x;
    const int ty = tid >> 4, tx = tid & 15;

    for (int idx = tid; idx < CD * 32; idx += 256) {
        int c = idx >> 5, c4 = (idx & 31) * 4;
        *(float4*)(Ws + c * PW + c4) = *(const float4*)(g_WoT + c * CD + c4);
        *(float4*)(Os + c * PW + c4) =
            *(const float4*)(g_O + ((size_t)(b * CD + c)) * NTOK + p0 + c4);
    }
    __syncthreads();

    float acc[8][8];
#pragma unroll
    for (int i = 0; i < 8; i++)
#pragma unroll
        for (int j = 0; j < 8; j++) acc[i][j] = 0.f;

#pragma unroll 4
    for (int c = 0; c < CD; c++) {
        float4 w0 = *(float4*)(Ws + c * PW + ty * 8);
        float4 w1 = *(float4*)(Ws + c * PW + ty * 8 + 4);
        float4 x0 = *(float4*)(Os + c * PW + tx * 8);
        float4 x1 = *(float4*)(Os + c * PW + tx * 8 + 4);
        float wr[8] = {w0.x, w0.y, w0.z, w0.w, w1.x, w1.y, w1.z, w1.w};
        float xr[8] = {x0.x, x0.y, x0.z, x0.w, x1.x, x1.y, x1.z, x1.w};
#pragma unroll
        for (int i = 0; i < 8; i++)
#pragma unroll
            for (int j = 0; j < 8; j++) acc[i][j] += wr[i] * xr[j];
    }

#pragma unroll
    for (int i = 0; i < 8; i++) {
        int o = ty * 8 + i;
        float bb = bo[o];
        const float* xr = x + ((size_t)(b * CD + o)) * NTOK + p0 + tx * 8;
        float4 xa = *(const float4*)(xr);
        float4 xb = *(const float4*)(xr + 4);
        float* r = out + ((size_t)(b * CD + o)) * NTOK + p0 + tx * 8;
        *(float4*)(r) = make_float4(acc[i][0] + bb + xa.x, acc[i][1] + bb + xa.y,
                                    acc[i][2] + bb + xa.z, acc[i][3] + bb + xa.w);
        *(float4*)(r + 4) = make_float4(acc[i][4] + bb + xb.x, acc[i][5] + bb + xb.y,
                                        acc[i][6] + bb + xb.z, acc[i][7] + bb + xb.w);
    }
}

// ---------------------------------------------------------------------------
extern "C" void kernel_launch(void* const* d_in, const int* in_sizes, int n_in,
                              void* d_out, int out_size) {
    const float* x  = (const float*)d_in[0];
    const float* Wq = (const float*)d_in[1];
    const float* bq = (const float*)d_in[2];
    const float* Wk = (const float*)d_in[3];
    const float* bk = (const float*)d_in[4];
    const float* Wv = (const float*)d_in[5];
    const float* bv = (const float*)d_in[6];
    const float* Wo = (const float*)d_in[7];
    const float* bo = (const float*)d_in[8];
    float* out = (float*)d_out;

    // Idempotent, called every launch (no static guards).
    cudaFuncSetAttribute(k_qkv,  cudaFuncAttributeMaxDynamicSharedMemorySize, SM_GEMM);
    cudaFuncSetAttribute(k_attn, cudaFuncAttributeMaxDynamicSharedMemorySize, SM_ATTN);
    cudaFuncSetAttribute(k_out,  cudaFuncAttributeMaxDynamicSharedMemorySize, SM_GEMM);

    k_transpose_w<<<4, 256>>>(Wq, Wk, Wv, Wo);
    k_qkv<<<dim3(NTOK / 128, BATCH), 256, SM_GEMM>>>(x, bq, bk, bv);
    k_attn<<<dim3(NTOK / BQ, BATCH), 256, SM_ATTN>>>();
    k_out<<<dim3(NTOK / 128, BATCH), 256, SM_GEMM>>>(x, bo, out);
}

// round 5
// speedup vs baseline: 5.6225x; 5.6225x over previous
#include <cuda_runtime.h>
#include <cuda_fp16.h>
#include <math.h>
#include <stdint.h>

constexpr int BATCH = 4;
constexpr int NTOK  = 4096;
constexpr int CD    = 128;
constexpr int BQ    = 128;   // queries per CTA
constexpr int BK    = 64;    // keys per iteration
constexpr int NIT   = NTOK / BK;

// ------------------------------------------------------------------ globals
__device__ float g_WT [3 * CD * CD];
__device__ float g_WoT[CD * CD];
__device__ __align__(16) unsigned short g_Qh[BATCH * NTOK * CD];  // fp16 [b][tok][d]
__device__ __align__(16) unsigned short g_Ql[BATCH * NTOK * CD];
__device__ __align__(16) unsigned short g_Kh[BATCH * NTOK * CD];
__device__ __align__(16) unsigned short g_Kl[BATCH * NTOK * CD];
__device__ __align__(16) unsigned short g_Vf[BATCH * NTOK * CD];
__device__ float g_O[BATCH * CD * NTOK];                          // [b][d][tok]

// ------------------------------------------------------------------ helpers
__device__ __forceinline__ uint32_t smem_u32(const void* p) {
    uint32_t a;
    asm("{ .reg .u64 t; cvta.to.shared.u64 t, %1; cvt.u32.u64 %0, t; }" : "=r"(a) : "l"(p));
    return a;
}
__device__ __forceinline__ void cpa16(uint32_t s, const void* g) {
    asm volatile("cp.async.cg.shared.global [%0], [%1], 16;" :: "r"(s), "l"(g));
}
#define CP_COMMIT() asm volatile("cp.async.commit_group;" ::: "memory")
#define CP_WAIT1()  asm volatile("cp.async.wait_group 1;"  ::: "memory")
#define CP_WAIT0()  asm volatile("cp.async.wait_group 0;"  ::: "memory")

__device__ __forceinline__ void ldsm4(uint32_t a, uint32_t* r) {
    asm volatile("ldmatrix.sync.aligned.m8n8.x4.shared.b16 {%0,%1,%2,%3}, [%4];"
        : "=r"(r[0]), "=r"(r[1]), "=r"(r[2]), "=r"(r[3]) : "r"(a));
}
__device__ __forceinline__ void ldsm4t(uint32_t a, uint32_t* r) {
    asm volatile("ldmatrix.sync.aligned.m8n8.x4.trans.shared.b16 {%0,%1,%2,%3}, [%4];"
        : "=r"(r[0]), "=r"(r[1]), "=r"(r[2]), "=r"(r[3]) : "r"(a));
}
__device__ __forceinline__ void mma16816(float* d, const uint32_t* a, uint32_t b0, uint32_t b1) {
    asm volatile("mma.sync.aligned.m16n8k16.row.col.f32.f16.f16.f32 "
        "{%0,%1,%2,%3}, {%4,%5,%6,%7}, {%8,%9}, {%0,%1,%2,%3};"
        : "+f"(d[0]), "+f"(d[1]), "+f"(d[2]), "+f"(d[3])
        : "r"(a[0]), "r"(a[1]), "r"(a[2]), "r"(a[3]), "r"(b0), "r"(b1));
}
__device__ __forceinline__ float ex2(float x) {
    float y;
    asm("ex2.approx.ftz.f32 %0, %1;" : "=f"(y) : "f"(x));
    return y;
}
__device__ __forceinline__ uint32_t packh2(float lo, float hi) {
    uint32_t d;
    asm("cvt.rn.f16x2.f32 %0, %1, %2;" : "=r"(d) : "f"(hi), "f"(lo));
    return d;
}
// fp16 hi/lo split of two floats -> two packed f16x2 (lo elem = first arg)
__device__ __forceinline__ void sp16(float a, float b, uint32_t& h, uint32_t& l) {
    __half ha = __float2half_rn(a), hb = __float2half_rn(b);
    float ra = a - __half2float(ha), rb = b - __half2float(hb);
    __half la = __float2half_rn(ra), lb = __float2half_rn(rb);
    h = ((uint32_t)__half_as_ushort(hb) << 16) | __half_as_ushort(ha);
    l = ((uint32_t)__half_as_ushort(lb) << 16) | __half_as_ushort(la);
}

// smem map for attention (fp16 rows of 256B, per-row sw128 swizzle on bits 4-6)
constexpr int SQH  = 0;
constexpr int SQL  = 32768;
constexpr int SKV  = 65536;        // 2 bufs x (Kh 16K | Kl 16K | V 16K)
constexpr int KVSTRIDE = 49152;
constexpr int SM_ATTN = SKV + 2 * KVSTRIDE;   // 163840

__device__ __forceinline__ uint32_t swz(int r, uint32_t colb) {
    return (uint32_t)r * 256 + (colb ^ (((uint32_t)(r & 7)) << 4));
}
__device__ __forceinline__ void load_tile(const unsigned short* __restrict__ g,
                                          uint32_t sbase, int rows, int tid) {
    int n = rows * 16;
    for (int i = tid; i < n; i += 256) {
        int r = i >> 4, c = i & 15;
        cpa16(sbase + swz(r, (uint32_t)c * 16), g + (size_t)r * CD + c * 8);
    }
}

// ------------------------------------------------------------------ weights
__global__ void k_transpose_w(const float* __restrict__ Wq, const float* __restrict__ Wk,
                              const float* __restrict__ Wv, const float* __restrict__ Wo) {
    const float* src; float* dst;
    int w = blockIdx.x;
    if      (w == 0) { src = Wq; dst = g_WT;           }
    else if (w == 1) { src = Wk; dst = g_WT + CD*CD;   }
    else if (w == 2) { src = Wv; dst = g_WT + 2*CD*CD; }
    else             { src = Wo; dst = g_WoT;          }
    for (int i = threadIdx.x; i < CD*CD; i += blockDim.x)
        dst[(i % CD) * CD + (i / CD)] = src[i];
}

// ------------------------------------------------------------------ QKV (fp32 GEMM -> fp16 splits)
constexpr int SM_GEMM = 2 * CD * (CD + 4) * 4;

__global__ __launch_bounds__(256, 1)
void k_qkv(const float* __restrict__ x, const float* __restrict__ bq,
           const float* __restrict__ bk, const float* __restrict__ bv) {
    extern __shared__ float smf[];
    float* Ws = smf;
    float* Xs = smf + CD * (CD + 4);
    constexpr int PW = CD + 4;
    const int b = blockIdx.y, p0 = blockIdx.x * 128, tid = threadIdx.x;
    const int ty = tid >> 4, tx = tid & 15;

    for (int i = tid; i < CD * 32; i += 256) {
        int c = i >> 5, c4 = (i & 31) * 4;
        *(float4*)(Xs + c*PW + c4) = *(const float4*)(x + ((size_t)(b*CD+c))*NTOK + p0 + c4);
    }
    for (int w = 0; w < 3; w++) {
        __syncthreads();
        for (int i = tid; i < CD * 32; i += 256) {
            int c = i >> 5, c4 = (i & 31) * 4;
            *(float4*)(Ws + c*PW + c4) = *(const float4*)(g_WT + w*CD*CD + c*CD + c4);
        }
        __syncthreads();
        float acc[8][8];
#pragma unroll
        for (int i = 0; i < 8; i++)
#pragma unroll
            for (int j = 0; j < 8; j++) acc[i][j] = 0.f;
#pragma unroll 4
        for (int c = 0; c < CD; c++) {
            float4 w0 = *(float4*)(Ws + c*PW + ty*8), w1 = *(float4*)(Ws + c*PW + ty*8 + 4);
            float4 x0 = *(float4*)(Xs + c*PW + tx*8), x1 = *(float4*)(Xs + c*PW + tx*8 + 4);
            float wr[8] = {w0.x,w0.y,w0.z,w0.w,w1.x,w1.y,w1.z,w1.w};
            float xr[8] = {x0.x,x0.y,x0.z,x0.w,x1.x,x1.y,x1.z,x1.w};
#pragma unroll
            for (int i = 0; i < 8; i++)
#pragma unroll
                for (int j = 0; j < 8; j++) acc[i][j] += wr[i] * xr[j];
        }
        const float* bias = (w == 0) ? bq : (w == 1) ? bk : bv;
#pragma unroll
        for (int i = 0; i < 8; i++) {
            float bb = bias[ty*8 + i];
#pragma unroll
            for (int j = 0; j < 8; j++) acc[i][j] += bb;
        }
        // token-major stores
        if (w < 2) {
            unsigned short* dh = (w == 0) ? g_Qh : g_Kh;
            unsigned short* dl = (w == 0) ? g_Ql : g_Kl;
#pragma unroll
            for (int j = 0; j < 8; j++) {
                uint32_t h[4], l[4];
#pragma unroll
                for (int ii = 0; ii < 4; ii++)
                    sp16(acc[2*ii][j], acc[2*ii+1][j], h[ii], l[ii]);
                size_t base = ((size_t)b*NTOK + p0 + tx*8 + j) * CD + ty*8;
                *(uint4*)(dh + base) = make_uint4(h[0], h[1], h[2], h[3]);
                *(uint4*)(dl + base) = make_uint4(l[0], l[1], l[2], l[3]);
            }
        } else {
#pragma unroll
            for (int j = 0; j < 8; j++) {
                uint32_t h[4], l[4];
#pragma unroll
                for (int ii = 0; ii < 4; ii++)
                    sp16(acc[2*ii][j], acc[2*ii+1][j], h[ii], l[ii]);
                size_t base = ((size_t)b*NTOK + p0 + tx*8 + j) * CD + ty*8;
                *(uint4*)(g_Vf + base) = make_uint4(h[0], h[1], h[2], h[3]);
            }
        }
    }
}

// ------------------------------------------------------------------ flash attention (mma.sync fp16)
__global__ __launch_bounds__(256, 1)
void k_attn_mma() {
    extern __shared__ char sm[];
    const uint32_t smb = smem_u32(sm);
    const int b = blockIdx.y, q0 = blockIdx.x * BQ, tid = threadIdx.x;
    const int wid = tid >> 5, lane = tid & 31;

    const unsigned short* Qhg = g_Qh + ((size_t)b*NTOK + q0) * CD;
    const unsigned short* Qlg = g_Ql + ((size_t)b*NTOK + q0) * CD;
    const unsigned short* Khg = g_Kh + (size_t)b*NTOK*CD;
    const unsigned short* Klg = g_Kl + (size_t)b*NTOK*CD;
    const unsigned short* Vg  = g_Vf + (size_t)b*NTOK*CD;

    // prologue: Q + KV0 | KV1
    load_tile(Qhg, smb + SQH, 128, tid);
    load_tile(Qlg, smb + SQL, 128, tid);
    load_tile(Khg, smb + SKV,         64, tid);
    load_tile(Klg, smb + SKV + 16384, 64, tid);
    load_tile(Vg,  smb + SKV + 32768, 64, tid);
    CP_COMMIT();
    load_tile(Khg + (size_t)BK*CD, smb + SKV + KVSTRIDE,         64, tid);
    load_tile(Klg + (size_t)BK*CD, smb + SKV + KVSTRIDE + 16384, 64, tid);
    load_tile(Vg  + (size_t)BK*CD, smb + SKV + KVSTRIDE + 32768, 64, tid);
    CP_COMMIT();

    const float L2E = 1.44269504f;
    float o[16][4];
#pragma unroll
    for (int i = 0; i < 16; i++)
#pragma unroll
        for (int j = 0; j < 4; j++) o[i][j] = 0.f;
    float m0 = -1e30f, m1 = -1e30f, l0 = 0.f, l1 = 0.f;

    const int qrow = (wid << 4) + (lane & 15);       // ldsm A row for this lane
    const uint32_t cbase = (uint32_t)((lane >> 4) << 4);  // +16B for upper half lanes

    for (int t = 0; t < NIT; t++) {
        if (t == NIT - 1) { CP_WAIT0(); } else { CP_WAIT1(); }
        __syncthreads();
        const uint32_t kv = smb + SKV + (t & 1) * KVSTRIDE;

        // ---- S = Qh*Kh + Qh*Kl + Ql*Kh   (16q x 64k per warp)
        float c[8][4];
#pragma unroll
        for (int i = 0; i < 8; i++)
#pragma unroll
            for (int j = 0; j < 4; j++) c[i][j] = 0.f;

#pragma unroll
        for (int ks = 0; ks < 8; ks++) {
            uint32_t colb = (uint32_t)(ks * 32) + cbase;
            uint32_t qoff = swz(qrow, colb);
            uint32_t ah[4], al[4];
            ldsm4(smb + SQH + qoff, ah);
            ldsm4(smb + SQL + qoff, al);
#pragma unroll
            for (int kg = 0; kg < 4; kg++) {
                int kr = kg * 16 + (lane & 15);
                uint32_t koff = swz(kr, colb);
                uint32_t kh[4], kl[4];
                ldsm4(kv + koff, kh);
                ldsm4(kv + 16384 + koff, kl);
                mma16816(c[2*kg],   ah, kh[0], kh[2]);
                mma16816(c[2*kg+1], ah, kh[1], kh[3]);
                mma16816(c[2*kg],   ah, kl[0], kl[2]);
                mma16816(c[2*kg+1], ah, kl[1], kl[3]);
                mma16816(c[2*kg],   al, kh[0], kh[2]);
                mma16816(c[2*kg+1], al, kh[1], kh[3]);
            }
        }

        // ---- online softmax (log2 domain)
#pragma unroll
        for (int i = 0; i < 8; i++)
#pragma unroll
            for (int j = 0; j < 4; j++) c[i][j] *= L2E;

        float mx0 = -1e30f, mx1 = -1e30f;
#pragma unroll
        for (int i = 0; i < 8; i++) {
            mx0 = fmaxf(mx0, fmaxf(c[i][0], c[i][1]));
            mx1 = fmaxf(mx1, fmaxf(c[i][2], c[i][3]));
        }
        mx0 = fmaxf(mx0, __shfl_xor_sync(0xffffffffu, mx0, 1));
        mx0 = fmaxf(mx0, __shfl_xor_sync(0xffffffffu, mx0, 2));
        mx1 = fmaxf(mx1, __shfl_xor_sync(0xffffffffu, mx1, 1));
        mx1 = fmaxf(mx1, __shfl_xor_sync(0xffffffffu, mx1, 2));

        float mn0 = fmaxf(m0, mx0), mn1 = fmaxf(m1, mx1);
        float sc0 = ex2(m0 - mn0),  sc1 = ex2(m1 - mn1);
        m0 = mn0; m1 = mn1;

        float p[8][4];
        float rs0 = 0.f, rs1 = 0.f;
#pragma unroll
        for (int i = 0; i < 8; i++) {
            p[i][0] = ex2(c[i][0] - mn0);
            p[i][1] = ex2(c[i][1] - mn0);
            p[i][2] = ex2(c[i][2] - mn1);
            p[i][3] = ex2(c[i][3] - mn1);
            rs0 += p[i][0] + p[i][1];
            rs1 += p[i][2] + p[i][3];
        }
        l0 = l0 * sc0 + rs0;
        l1 = l1 * sc1 + rs1;
#pragma unroll
        for (int i = 0; i < 16; i++) {
            o[i][0] *= sc0; o[i][1] *= sc0;
            o[i][2] *= sc1; o[i][3] *= sc1;
        }

        // pack P into A fragments (FA2 identity)
        uint32_t pa[16];
#pragma unroll
        for (int ks2 = 0; ks2 < 4; ks2++) {
            pa[ks2*4+0] = packh2(p[2*ks2][0],   p[2*ks2][1]);
            pa[ks2*4+1] = packh2(p[2*ks2][2],   p[2*ks2][3]);
            pa[ks2*4+2] = packh2(p[2*ks2+1][0], p[2*ks2+1][1]);
            pa[ks2*4+3] = packh2(p[2*ks2+1][2], p[2*ks2+1][3]);
        }

        // ---- O += P * V  (16q x 128d per warp)
        const uint32_t vb = kv + 32768;
#pragma unroll
        for (int ks2 = 0; ks2 < 4; ks2++) {
            int vr = ks2 * 16 + (lane & 15);
#pragma unroll
            for (int dg = 0; dg < 8; dg++) {
                uint32_t voff = swz(vr, (uint32_t)(dg * 32) + cbase);
                uint32_t v[4];
                ldsm4t(vb + voff, v);
                mma16816(o[2*dg],   pa + ks2*4, v[0], v[1]);
                mma16816(o[2*dg+1], pa + ks2*4, v[2], v[3]);
            }
        }

        __syncthreads();
        if (t + 2 < NIT) {
            size_t off = (size_t)(t + 2) * BK * CD;
            uint32_t sb = smb + SKV + (t & 1) * KVSTRIDE;
            load_tile(Khg + off, sb,         64, tid);
            load_tile(Klg + off, sb + 16384, 64, tid);
            load_tile(Vg  + off, sb + 32768, 64, tid);
            CP_COMMIT();
        }
    }

    // ---- epilogue
    l0 += __shfl_xor_sync(0xffffffffu, l0, 1);
    l0 += __shfl_xor_sync(0xffffffffu, l0, 2);
    l1 += __shfl_xor_sync(0xffffffffu, l1, 1);
    l1 += __shfl_xor_sync(0xffffffffu, l1, 2);
    float inv0 = 1.f / l0, inv1 = 1.f / l1;

    int qr0 = q0 + wid * 16 + (lane >> 2);
    int qr1 = qr0 + 8;
    float* Ob = g_O + (size_t)b * CD * NTOK;
#pragma unroll
    for (int nt = 0; nt < 16; nt++) {
        int d0 = nt * 8 + (lane & 3) * 2;
        Ob[(size_t)d0       * NTOK + qr0] = o[nt][0] * inv0;
        Ob[(size_t)(d0 + 1) * NTOK + qr0] = o[nt][1] * inv0;
        Ob[(size_t)d0       * NTOK + qr1] = o[nt][2] * inv1;
        Ob[(size_t)(d0 + 1) * NTOK + qr1] = o[nt][3] * inv1;
    }
}

// ------------------------------------------------------------------ out proj + residual
__global__ __launch_bounds__(256, 1)
void k_out(const float* __restrict__ x, const float* __restrict__ bo,
           float* __restrict__ out) {
    extern __shared__ float smf[];
    float* Ws = smf;
    float* Os = smf + CD * (CD + 4);
    constexpr int PW = CD + 4;
    const int b = blockIdx.y, p0 = blockIdx.x * 128, tid = threadIdx.x;
    const int ty = tid >> 4, tx = tid & 15;

    for (int i = tid; i < CD * 32; i += 256) {
        int c = i >> 5, c4 = (i & 31) * 4;
        *(float4*)(Ws + c*PW + c4) = *(const float4*)(g_WoT + c*CD + c4);
        *(float4*)(Os + c*PW + c4) = *(const float4*)(g_O + ((size_t)(b*CD+c))*NTOK + p0 + c4);
    }
    __syncthreads();
    float acc[8][8];
#pragma unroll
    for (int i = 0; i < 8; i++)
#pragma unroll
        for (int j = 0; j < 8; j++) acc[i][j] = 0.f;
#pragma unroll 4
    for (int c = 0; c < CD; c++) {
        float4 w0 = *(float4*)(Ws + c*PW + ty*8), w1 = *(float4*)(Ws + c*PW + ty*8 + 4);
        float4 x0 = *(float4*)(Os + c*PW + tx*8), x1 = *(float4*)(Os + c*PW + tx*8 + 4);
        float wr[8] = {w0.x,w0.y,w0.z,w0.w,w1.x,w1.y,w1.z,w1.w};
        float xr[8] = {x0.x,x0.y,x0.z,x0.w,x1.x,x1.y,x1.z,x1.w};
#pragma unroll
        for (int i = 0; i < 8; i++)
#pragma unroll
            for (int j = 0; j < 8; j++) acc[i][j] += wr[i] * xr[j];
    }
#pragma unroll
    for (int i = 0; i < 8; i++) {
        int oc = ty*8 + i;
        float bb = bo[oc];
        const float* xr = x + ((size_t)(b*CD+oc))*NTOK + p0 + tx*8;
        float4 xa = *(const float4*)(xr), xb = *(const float4*)(xr + 4);
        float* r = out + ((size_t)(b*CD+oc))*NTOK + p0 + tx*8;
        *(float4*)(r)   = make_float4(acc[i][0]+bb+xa.x, acc[i][1]+bb+xa.y,
                                      acc[i][2]+bb+xa.z, acc[i][3]+bb+xa.w);
        *(float4*)(r+4) = make_float4(acc[i][4]+bb+xb.x, acc[i][5]+bb+xb.y,
                                      acc[i][6]+bb+xb.z, acc[i][7]+bb+xb.w);
    }
}

// ------------------------------------------------------------------ launch
extern "C" void kernel_launch(void* const* d_in, const int* in_sizes, int n_in,
                              void* d_out, int out_size) {
    const float* x  = (const float*)d_in[0];
    const float* Wq = (const float*)d_in[1];
    const float* bq = (const float*)d_in[2];
    const float* Wk = (const float*)d_in[3];
    const float* bk = (const float*)d_in[4];
    const float* Wv = (const float*)d_in[5];
    const float* bv = (const float*)d_in[6];
    const float* Wo = (const float*)d_in[7];
    const float* bo = (const float*)d_in[8];
    float* out = (float*)d_out;

    cudaFuncSetAttribute(k_qkv,      cudaFuncAttributeMaxDynamicSharedMemorySize, SM_GEMM);
    cudaFuncSetAttribute(k_attn_mma, cudaFuncAttributeMaxDynamicSharedMemorySize, SM_ATTN);
    cudaFuncSetAttribute(k_out,      cudaFuncAttributeMaxDynamicSharedMemorySize, SM_GEMM);

    k_transpose_w<<<4, 256>>>(Wq, Wk, Wv, Wo);
    k_qkv<<<dim3(NTOK / 128, BATCH), 256, SM_GEMM>>>(x, bq, bk, bv);
    k_attn_mma<<<dim3(NTOK / BQ, BATCH), 256, SM_ATTN>>>();
    k_out<<<dim3(NTOK / 128, BATCH), 256, SM_GEMM>>>(x, bo, out);
}